// round 1
// baseline (speedup 1.0000x reference)
#include <cuda_runtime.h>
#include <math.h>

#define IMG 256
#define MAX_R 64
#define N_AG 2047
#define N_OB 2048
#define N_ENT (N_AG + N_OB)
#define FOVH 0.7853981633974483f   /* pi/4 = FOV/2 */

__global__ void init_kernel(unsigned int* out) {
    int i = blockIdx.x * blockDim.x + threadIdx.x;
    if (i < IMG * IMG) out[i] = __float_as_uint(1.0f);
}

__global__ void splat_kernel(const float* __restrict__ agent,
                             const float* __restrict__ goal,
                             const float* __restrict__ others,
                             const float* __restrict__ obs,
                             unsigned int* __restrict__ out) {
    int e = blockIdx.x;

    // camera rotation (computed redundantly per block; 10 flops, negligible)
    float ax = agent[0], ay = agent[1];
    float vx = goal[0] - ax, vy = goal[1] - ay;
    float inv = 1.0f / (sqrtf(vx * vx + vy * vy) + 1e-8f);
    vx *= inv; vy *= inv;
    float c = vy, s = vx;

    float ex, ey, r, h;
    if (e < N_AG) {
        ex = others[2 * e];
        ey = others[2 * e + 1];
        r  = 0.05f;
        h  = 0.2f;
    } else {
        int o = e - N_AG;
        ex = obs[3 * o];
        ey = obs[3 * o + 1];
        r  = obs[3 * o + 2];
        h  = 0.5f;
    }

    float rx = ex - ax, ry = ey - ay;
    float camx =  c * rx + s * ry;
    float camy = -s * rx + c * ry;
    float dist = sqrtf(camx * camx + camy * camy);
    float angle = atan2f(camx, camy);

    bool valid = (camy >= 0.0f) && (dist <= 3.0f) && (fabsf(angle) <= FOVH);
    if (!valid) return;

    float pixel_x = angle / FOVH * 0.5f;
    int pxi = (int)floorf((pixel_x + 0.5f) * (float)IMG);
    int pr  = (int)floorf(r / (dist + 1e-8f) * (float)IMG * 0.5f);
    pr = min(max(pr, 1), MAX_R);

    float depth = fminf(dist / 3.0f, 1.0f) * (1.0f - h * 0.3f);
    depth = fmaxf(depth, 0.0f);
    unsigned int dbits = __float_as_uint(depth);

    int side = 2 * pr + 1;
    int area = side * side;
    int pr2  = pr * pr;

    for (int t = threadIdx.x; t < area; t += blockDim.x) {
        int dy = t / side - pr;
        int dx = t % side - pr;
        if (dx * dx + dy * dy > pr2) continue;
        int px = pxi + dx;
        if (px < 0 || px >= IMG) continue;
        int py = IMG / 2 + dy;          // always in [64,192], in-bounds
        atomicMin(&out[py * IMG + px], dbits);
    }
}

extern "C" void kernel_launch(void* const* d_in, const int* in_sizes, int n_in,
                              void* d_out, int out_size) {
    const float* agent  = (const float*)d_in[0];
    const float* goal   = (const float*)d_in[1];
    const float* others = (const float*)d_in[2];
    const float* obs    = (const float*)d_in[3];
    unsigned int* out   = (unsigned int*)d_out;

    init_kernel<<<(IMG * IMG + 255) / 256, 256>>>(out);
    splat_kernel<<<N_ENT, 128>>>(agent, goal, others, obs, out);
}